// round 6
// baseline (speedup 1.0000x reference)
#include <cuda_runtime.h>
#include <cstdint>
#include <math.h>

#define TOKENS 16384
#define KDIM   2048
#define NEXP   64
#define TM     64                      // tokens per CTA
#define KC     64                      // K elems per chunk
#define NCHUNK (KDIM / KC)             // 32
#define SA     144                     // smem row stride bytes (conflict-free ldmatrix)
#define OFF_AL (64 * SA)               // 9216
#define OFF_BH (2 * 64 * SA)           // 18432
#define OFF_BL (2 * 64 * SA + 64 * SA) // 27648
#define STAGE  (4 * 64 * SA)           // 36864 per stage
#define DYN_SMEM (2 * STAGE)           // 73728 double-buffered -> 2 CTAs/SM
#define RESCUE_TH 3e-4f

typedef unsigned int u32;

// Pre-split W planes (bf16 pairs packed in u32), written by prep kernel each call.
__device__ __align__(16) u32 g_Whi[NEXP * KDIM / 2];
__device__ __align__(16) u32 g_Wlo[NEXP * KDIM / 2];

// ---------------- helpers ----------------
static __device__ __forceinline__ u32 smem_u32(const void* p) {
    u32 a;
    asm("{ .reg .u64 t; cvta.to.shared.u64 t, %1; cvt.u32.u64 %0, t; }" : "=r"(a) : "l"(p));
    return a;
}
static __device__ __forceinline__ u32 cvt_bf2(float f0, float f1) {
    u32 r;
    asm("cvt.rn.bf16x2.f32 %0, %1, %2;" : "=r"(r) : "f"(f1), "f"(f0));
    return r;
}
static __device__ __forceinline__ void sts64(u32 a, u32 lo, u32 hi) {
    asm volatile("st.shared.v2.b32 [%0], {%1,%2};" :: "r"(a), "r"(lo), "r"(hi) : "memory");
}
static __device__ __forceinline__ void cpasync16(u32 dst, const void* src) {
    asm volatile("cp.async.cg.shared.global [%0], [%1], 16;" :: "r"(dst), "l"(src) : "memory");
}
#define CP_COMMIT() asm volatile("cp.async.commit_group;" ::: "memory")
#define CP_WAIT0()  asm volatile("cp.async.wait_group 0;" ::: "memory")
static __device__ __forceinline__ void ldm_x4(u32* r, u32 a) {
    asm volatile("ldmatrix.sync.aligned.m8n8.x4.shared.b16 {%0,%1,%2,%3}, [%4];"
                 : "=r"(r[0]), "=r"(r[1]), "=r"(r[2]), "=r"(r[3]) : "r"(a));
}
static __device__ __forceinline__ void mma_bf16(float* c, const u32* a, const u32* b) {
    asm volatile("mma.sync.aligned.m16n8k16.row.col.f32.bf16.bf16.f32 "
                 "{%0,%1,%2,%3}, {%4,%5,%6,%7}, {%8,%9}, {%0,%1,%2,%3};"
                 : "+f"(c[0]), "+f"(c[1]), "+f"(c[2]), "+f"(c[3])
                 : "r"(a[0]), "r"(a[1]), "r"(a[2]), "r"(a[3]), "r"(b[0]), "r"(b[1]));
}

// ---------------- W pre-split kernel ----------------
__global__ void prep_w(const float* __restrict__ W) {
    int p = blockIdx.x * blockDim.x + threadIdx.x;   // pair index, 65536 total
    float2 xy = ((const float2*)W)[p];
    u32 h = cvt_bf2(xy.x, xy.y);
    float h0 = __uint_as_float(h << 16);
    float h1 = __uint_as_float(h & 0xffff0000u);
    u32 l = cvt_bf2(xy.x - h0, xy.y - h1);
    g_Whi[p] = h;
    g_Wlo[p] = l;
}

// ---------------- exact fp32 rescoring ----------------
__device__ __noinline__ float exact_dot(const float* __restrict__ xr, const float* __restrict__ wr) {
    float a0 = 0.f, a1 = 0.f, a2 = 0.f, a3 = 0.f;
    for (int k = 0; k < KDIM; k += 4) {
        a0 = fmaf(__ldg(xr + k + 0), __ldg(wr + k + 0), a0);
        a1 = fmaf(__ldg(xr + k + 1), __ldg(wr + k + 1), a1);
        a2 = fmaf(__ldg(xr + k + 2), __ldg(wr + k + 2), a2);
        a3 = fmaf(__ldg(xr + k + 3), __ldg(wr + k + 3), a3);
    }
    return (a0 + a1) + (a2 + a3);
}

// ---------------- main kernel ----------------
__global__ __launch_bounds__(256, 2)
void router_mma(const float* __restrict__ x,
                const float* __restrict__ W,
                const float* __restrict__ bias,
                float* __restrict__ out)
{
    extern __shared__ __align__(16) char dsmp[];
    const u32 sb = smem_u32(dsmp);
    __shared__ float s_bias[NEXP];

    const int tid  = threadIdx.x;
    const int wid  = tid >> 5;
    const int lane = tid & 31;
    const int wm   = wid & 1;          // M block (32 tokens)
    const int wn   = wid >> 1;         // N block (16 experts)
    const int tokBase = blockIdx.x * TM;

    if (tid < NEXP) s_bias[tid] = bias[tid];

    float acc[2][2][4];                // [mt m16][nt n8][frag]
#pragma unroll
    for (int i = 0; i < 2; i++)
#pragma unroll
        for (int j = 0; j < 2; j++)
#pragma unroll
            for (int q = 0; q < 4; q++) acc[i][j][q] = 0.f;

    float4 px[4];                      // x prefetch
    const float4* xp = (const float4*)x;
    const uint4* whp = (const uint4*)g_Whi;
    const uint4* wlp = (const uint4*)g_Wlo;

    // thread's fixed load mapping
    const int xrow = tid >> 2, xc4 = tid & 3;         // A: 64 rows x 16 float4; 4/thread
    const int brow0 = tid >> 3, bc16 = tid & 7;       // B: rows tid>>3, +32

#define LOAD_PX(c)                                                                  \
    {                                                                               \
        _Pragma("unroll")                                                           \
        for (int r = 0; r < 4; r++)                                                 \
            px[r] = xp[(size_t)(tokBase + xrow) * (KDIM / 4) + (c) * 16 + xc4 + 4 * r]; \
    }

#define ISSUE_B(c, st)                                                              \
    {                                                                               \
        _Pragma("unroll")                                                           \
        for (int r = 0; r < 2; r++) {                                               \
            int row = brow0 + r * 32;                                               \
            u32 d = sb + (st) * STAGE + OFF_BH + (u32)(row * SA + bc16 * 16);       \
            int idx = row * (KDIM / 8) + (c) * 8 + bc16;                            \
            cpasync16(d, whp + idx);                                                \
            cpasync16(d + (OFF_BL - OFF_BH), wlp + idx);                            \
        }                                                                           \
        CP_COMMIT();                                                                \
    }

#define STS_A(st)                                                                   \
    {                                                                               \
        _Pragma("unroll")                                                           \
        for (int r = 0; r < 4; r++) {                                               \
            u32 a = sb + (st) * STAGE + (u32)(xrow * SA + (xc4 + 4 * r) * 8);       \
            float4 v = px[r];                                                       \
            u32 h01 = cvt_bf2(v.x, v.y), h23 = cvt_bf2(v.z, v.w);                   \
            float g0 = __uint_as_float(h01 << 16), g1 = __uint_as_float(h01 & 0xffff0000u); \
            float g2 = __uint_as_float(h23 << 16), g3 = __uint_as_float(h23 & 0xffff0000u); \
            u32 l01 = cvt_bf2(v.x - g0, v.y - g1), l23 = cvt_bf2(v.z - g2, v.w - g3);       \
            sts64(a, h01, h23);                                                     \
            sts64(a + OFF_AL, l01, l23);                                            \
        }                                                                           \
    }

    // ldmatrix base offsets (stage-relative)
    const u32 aOff = (u32)((wm * 32 + (lane & 15)) * SA + (lane >> 4) * 16);
    const u32 bOff = (u32)(OFF_BH + (wn * 16 + ((lane >> 4) & 1) * 8 + (lane & 7)) * SA +
                           ((lane >> 3) & 1) * 16);

    // ---------------- prologue ----------------
    ISSUE_B(0, 0);
    LOAD_PX(0);
    STS_A(0);
    LOAD_PX(1);

    // ---------------- pipelined main loop ----------------
    for (int c = 0; c < NCHUNK; c++) {
        const int cur = c & 1, nxt = cur ^ 1;
        CP_WAIT0();
        __syncthreads();

        if (c + 1 < NCHUNK) ISSUE_B(c + 1, nxt);

        const u32 aAddr = sb + cur * STAGE + aOff;
        const u32 bAddr = sb + cur * STAGE + bOff;
#pragma unroll
        for (int ks = 0; ks < 4; ks++) {
            const u32 kb = ks * 32;
            u32 Ah[2][4], Al[2][4], Bh[4], Bl[4];
#pragma unroll
            for (int mt = 0; mt < 2; mt++) {
                ldm_x4(Ah[mt], aAddr + mt * (16 * SA) + kb);
                ldm_x4(Al[mt], aAddr + OFF_AL + mt * (16 * SA) + kb);
            }
            ldm_x4(Bh, bAddr + kb);
            ldm_x4(Bl, bAddr + (OFF_BL - OFF_BH) + kb);
#pragma unroll
            for (int mt = 0; mt < 2; mt++)
#pragma unroll
                for (int nt = 0; nt < 2; nt++) {
                    mma_bf16(acc[mt][nt], Ah[mt], &Bh[nt * 2]);
                    mma_bf16(acc[mt][nt], Ah[mt], &Bl[nt * 2]);
                    mma_bf16(acc[mt][nt], Al[mt], &Bh[nt * 2]);
                }
        }

        if (c + 1 < NCHUNK) STS_A(nxt);
        if (c + 2 < NCHUNK) LOAD_PX(c + 2);
    }

    // ---------------- epilogue ----------------
    __syncthreads();
    float* ls = (float*)dsmp;            // logits staging [64][65]
#pragma unroll
    for (int mt = 0; mt < 2; mt++)
#pragma unroll
        for (int nt = 0; nt < 2; nt++) {
            const int row = wm * 32 + mt * 16 + (lane >> 2);
            const int col = wn * 16 + nt * 8 + (lane & 3) * 2;
            ls[row * 65 + col]           = acc[mt][nt][0] + s_bias[col];
            ls[row * 65 + col + 1]       = acc[mt][nt][1] + s_bias[col + 1];
            ls[(row + 8) * 65 + col]     = acc[mt][nt][2] + s_bias[col];
            ls[(row + 8) * 65 + col + 1] = acc[mt][nt][3] + s_bias[col + 1];
        }
    __syncthreads();

    float* probs_out  = out;
    float* idx_out    = out + (size_t)TOKENS * 2;
    float* logits_out = out + (size_t)TOKENS * 4;

    // coalesced logits store: 1024 float4 per block, 4 per thread
#pragma unroll
    for (int r = 0; r < 4; r++) {
        int s  = tid + 256 * r;
        int t  = s >> 4;
        int e4 = s & 15;
        const float* lr = &ls[t * 65 + e4 * 4];
        *(float4*)(logits_out + (size_t)(tokBase + t) * NEXP + e4 * 4) =
            make_float4(lr[0], lr[1], lr[2], lr[3]);
    }

    // top-2 + softmax (+ exact rescue): one thread per token
    if (tid < TM) {
        const int t = tid;
        const int gt = tokBase + t;
        const float* lr = &ls[t * 65];
        float m1 = -INFINITY, m2 = -INFINITY, m3 = -INFINITY;
        int i1 = 0, i2 = 0;
#pragma unroll
        for (int e = 0; e < NEXP; e++) {
            const float v = lr[e];
            if (v > m1)      { m3 = m2; m2 = m1; i2 = i1; m1 = v; i1 = e; }
            else if (v > m2) { m3 = m2; m2 = v; i2 = e; }
            else if (v > m3) { m3 = v; }
        }
        float p1v = m1, p2v = m2;

        if ((m1 - m2 < RESCUE_TH) || (m2 - m3 < RESCUE_TH)) {
            const float thr = m2 - RESCUE_TH;
            float e1 = -INFINITY, e2 = -INFINITY;
            int j1 = 0, j2 = 0;
            const float* xr = x + (size_t)gt * KDIM;
#pragma unroll 1
            for (int e = 0; e < NEXP; e++) {
                if (lr[e] > thr) {
                    float ex = exact_dot(xr, W + (size_t)e * KDIM) + s_bias[e];
                    if (ex > e1)      { e2 = e1; j2 = j1; e1 = ex; j1 = e; }
                    else if (ex > e2) { e2 = ex; j2 = e; }
                }
            }
            i1 = j1; i2 = j2; p1v = e1; p2v = e2;
        }

        const float ex2 = expf(p2v - p1v);
        const float inv = 1.0f / (1.0f + ex2);
        probs_out[gt * 2 + 0] = inv;
        probs_out[gt * 2 + 1] = ex2 * inv;
        idx_out[gt * 2 + 0] = (float)i1;
        idx_out[gt * 2 + 1] = (float)i2;
    }
}

extern "C" void kernel_launch(void* const* d_in, const int* in_sizes, int n_in,
                              void* d_out, int out_size)
{
    const float* x = (const float*)d_in[0];
    const float* W = (const float*)d_in[1];
    const float* b = (const float*)d_in[2];
    float* out = (float*)d_out;

    cudaFuncSetAttribute(router_mma, cudaFuncAttributeMaxDynamicSharedMemorySize, DYN_SMEM);
    prep_w<<<256, 256>>>(W);
    router_mma<<<TOKENS / TM, 256, DYN_SMEM>>>(x, W, b, out);
}